// round 17
// baseline (speedup 1.0000x reference)
#include <cuda_runtime.h>
#include <cstdint>

#define IMG_H 480
#define IMG_W 640
#define NPIX (IMG_H * IMG_W)
#define NB 16
#define NTHR 128
#define BLK_X 600                         // 600 * 128 threads * 4 px = 307200 = NPIX
#define NBLOCKS (BLK_X * 2)
#define DEPTH 3                           // cp.async pipeline stages

__device__ double       g_sum;
__device__ unsigned int g_count;

__device__ __forceinline__ void cp_async4(uint32_t dst, const float* src) {
    asm volatile("cp.async.ca.shared.global [%0], [%1], 4;"
                 :: "r"(dst), "l"(src));
}
__device__ __forceinline__ void cp_commit() {
    asm volatile("cp.async.commit_group;" ::: "memory");
}
template <int N>
__device__ __forceinline__ void cp_wait() {
    asm volatile("cp.async.wait_group %0;" :: "n"(N) : "memory");
}

// ---------------------------------------------------------------------------
// Issue stage for batch b_: coords + 16 cp.asyncs into smem stage s_=b_%DEPTH,
// commit the group, refill the d4 source ring for b_+DEPTH.
// Fully-unrolled caller => b_ is a compile-time constant after inlining, so
// the stage-array indexing stays in registers.
// ---------------------------------------------------------------------------
__device__ __forceinline__ void issue_batch(
    int b_, int tid, float uf, float vf, int p,
    const float* __restrict__ sMC,
    const float* __restrict__ dsrc,
    const float* __restrict__ ddst,
    uint32_t tapbase,
    float4 (&d4buf)[DEPTH],
    float (&wxs)[DEPTH][4], float (&wys)[DEPTH][4], float (&dds)[DEPTH][4]) {

    const int s_ = b_ % DEPTH;
    const float* mc = &sMC[b_ * 12];
    const float P00 = mc[0], P01 = mc[1], P02 = mc[2];
    const float P10 = mc[3], P11 = mc[4], P12 = mc[5];
    const float P20 = mc[6], P21 = mc[7], P22 = mc[8];
    const float c0  = mc[9], c1  = mc[10], c2 = mc[11];

    const float4 d4 = d4buf[s_];
    const float dvp[4] = { d4.x, d4.y, d4.z, d4.w };
    const float* __restrict__ plane = ddst + b_ * NPIX;

    float bx = fmaf(P00, uf, fmaf(P01, vf, P02));
    float by = fmaf(P10, uf, fmaf(P11, vf, P12));
    float bd = fmaf(P20, uf, fmaf(P21, vf, P22));

#pragma unroll
    for (int j = 0; j < 4; j++) {
        float uu = fmaf(dvp[j], bx, c0);
        float vv = fmaf(dvp[j], by, c1);
        float d  = fmaf(dvp[j], bd, c2);
        dds[s_][j] = d;

        float denom = fmaxf(d, 0.0f) + 1e-12f;
        float r;
        asm("rcp.approx.ftz.f32 %0, %1;" : "=f"(r) : "f"(denom));

        float x = fmaf(uu, r, -0.5f);
        float y = fmaf(vv, r, -0.5f);
        x = fminf(fmaxf(x, 0.0f), (float)(IMG_W - 1));
        y = fminf(fmaxf(y, 0.0f), (float)(IMG_H - 1));

        int x0 = (int)x;                 // x >= 0 -> trunc == floor
        int y0 = (int)y;
        wxs[s_][j] = x - (float)x0;
        wys[s_][j] = y - (float)y0;
        int x1 = min(x0 + 1, IMG_W - 1);
        int y1 = min(y0 + 1, IMG_H - 1);

        const float* r0 = plane + y0 * IMG_W;
        const float* r1 = plane + y1 * IMG_W;
        uint32_t dst = tapbase + (uint32_t)(((s_ * 16 + j * 4) * NTHR + tid) * 4);
        cp_async4(dst + 0u * NTHR * 4u, r0 + x0);
        cp_async4(dst + 1u * NTHR * 4u, r0 + x1);
        cp_async4(dst + 2u * NTHR * 4u, r1 + x0);
        cp_async4(dst + 3u * NTHR * 4u, r1 + x1);

        bx += P00; by += P10; bd += P20;
    }
    cp_commit();

    if (b_ + DEPTH < NB)
        d4buf[s_] = __ldg((const float4*)(dsrc + (b_ + DEPTH) * NPIX + p));
}

// ---------------------------------------------------------------------------
// 4 pixels per thread. Gather taps via cp.async (register-free, explicit
// async groups ptxas cannot re-serialize), staged in smem, depth-3 pipeline:
//   iter b: wait(stage b) -> consume b -> issue(b+3)
// Uniform control flow: clamped rcp path computes the d<=0 corner case
// exactly (coords saturate by sign, wx=wy=0). blockIdx.y = direction.
// ---------------------------------------------------------------------------
__global__ __launch_bounds__(NTHR)
void pdsl_fused(const float* __restrict__ depth0,
                const float* __restrict__ depth1,
                const float* __restrict__ R0, const float* __restrict__ t0,
                const float* __restrict__ R1, const float* __restrict__ t1,
                const float* __restrict__ Kp,
                float* __restrict__ out) {
    __shared__ float sMC[NB * 12];            // per batch: P[9] (pre-scaled), c[3]
    __shared__ float sTap[DEPTH][16][NTHR];   // [stage][px*4+tap][tid] : 24 KB
    const int tid = threadIdx.x;
    const int dir = blockIdx.y;

    const float* __restrict__ dsrc = dir ? depth1 : depth0;
    const float* __restrict__ ddst = dir ? depth0 : depth1;

    // ---- fold transforms (threads 0..15, one batch each) ----
    if (tid < NB) {
        int b = tid;

        float K[9];
#pragma unroll
        for (int i = 0; i < 9; i++) K[i] = Kp[i];

        // analytic 3x3 inverse of K
        float det = K[0] * (K[4] * K[8] - K[5] * K[7])
                  - K[1] * (K[3] * K[8] - K[5] * K[6])
                  + K[2] * (K[3] * K[7] - K[4] * K[6]);
        float id = 1.0f / det;
        float Ki[9];
        Ki[0] = (K[4] * K[8] - K[5] * K[7]) * id;
        Ki[1] = (K[2] * K[7] - K[1] * K[8]) * id;
        Ki[2] = (K[1] * K[5] - K[2] * K[4]) * id;
        Ki[3] = (K[5] * K[6] - K[3] * K[8]) * id;
        Ki[4] = (K[0] * K[8] - K[2] * K[6]) * id;
        Ki[5] = (K[2] * K[3] - K[0] * K[5]) * id;
        Ki[6] = (K[3] * K[7] - K[4] * K[6]) * id;
        Ki[7] = (K[1] * K[6] - K[0] * K[7]) * id;
        Ki[8] = (K[0] * K[4] - K[1] * K[3]) * id;

        const float* Rs = (dir == 0 ? R0 : R1) + b * 9;
        const float* Rd = (dir == 0 ? R1 : R0) + b * 9;
        const float* ts = (dir == 0 ? t0 : t1) + b * 3;
        const float* td = (dir == 0 ? t1 : t0) + b * 3;

        float A[9];  // Rd * Rs^T
#pragma unroll
        for (int i = 0; i < 3; i++)
#pragma unroll
            for (int j = 0; j < 3; j++)
                A[i * 3 + j] = Rd[i * 3 + 0] * Rs[j * 3 + 0]
                             + Rd[i * 3 + 1] * Rs[j * 3 + 1]
                             + Rd[i * 3 + 2] * Rs[j * 3 + 2];
        float M[9];  // K * A
#pragma unroll
        for (int i = 0; i < 3; i++)
#pragma unroll
            for (int j = 0; j < 3; j++)
                M[i * 3 + j] = K[i * 3 + 0] * A[0 * 3 + j]
                             + K[i * 3 + 1] * A[1 * 3 + j]
                             + K[i * 3 + 2] * A[2 * 3 + j];

        // fold grid-sample normalization: x = (u/d)*W/(W-1) - 0.5
        const float rs[3] = { (float)IMG_W / (float)(IMG_W - 1),
                              (float)IMG_H / (float)(IMG_H - 1), 1.0f };

        float* mc = &sMC[b * 12];
#pragma unroll
        for (int i = 0; i < 3; i++)          // P = rs[i] * (M * Ki)
#pragma unroll
            for (int j = 0; j < 3; j++)
                mc[i * 3 + j] = rs[i] * (M[i * 3 + 0] * Ki[0 * 3 + j]
                                       + M[i * 3 + 1] * Ki[1 * 3 + j]
                                       + M[i * 3 + 2] * Ki[2 * 3 + j]);
#pragma unroll
        for (int i = 0; i < 3; i++) {        // c = rs[i] * (K*td - M*ts)
            float Ktd = K[i * 3 + 0] * td[0] + K[i * 3 + 1] * td[1] + K[i * 3 + 2] * td[2];
            mc[9 + i] = rs[i] * (Ktd - (M[i * 3 + 0] * ts[0]
                                      + M[i * 3 + 1] * ts[1]
                                      + M[i * 3 + 2] * ts[2]));
        }
    }

    const int tile = blockIdx.x * NTHR + tid;        // 0..76799
    const int p    = tile * 4;                       // 640 % 4 == 0: in-row quad
    const int vy   = p / IMG_W;
    const int ux   = p - vy * IMG_W;
    const float uf = (float)ux;
    const float vf = (float)vy;

    // source-depth prefetch ring (depth DEPTH); overlaps with the fold above
    float4 d4buf[DEPTH];
#pragma unroll
    for (int i = 0; i < DEPTH; i++)
        d4buf[i] = __ldg((const float4*)(dsrc + i * NPIX + p));

    __syncthreads();

    const uint32_t tapbase = (uint32_t)__cvta_generic_to_shared(&sTap[0][0][0]);

    // pipeline carry state: weights + depth per stage per pixel
    float wxs[DEPTH][4], wys[DEPTH][4], dds[DEPTH][4];

    float acc = 0.0f;

    // prologue: fill the pipeline
#pragma unroll
    for (int b = 0; b < DEPTH; b++)
        issue_batch(b, tid, uf, vf, p, sMC, dsrc, ddst, tapbase, d4buf, wxs, wys, dds);

#pragma unroll
    for (int b = 0; b < NB; b++) {
        // wait until group b has landed: allowed pending = min(DEPTH-1, NB-1-b)
        if (NB - 1 - b >= DEPTH - 1)      cp_wait<DEPTH - 1>();
        else if (NB - 1 - b == 1)         cp_wait<1>();
        else                              cp_wait<0>();

        const int s = b % DEPTH;
#pragma unroll
        for (int j = 0; j < 4; j++) {
            float v00 = sTap[s][j * 4 + 0][tid];
            float v01 = sTap[s][j * 4 + 1][tid];
            float v10 = sTap[s][j * 4 + 2][tid];
            float v11 = sTap[s][j * 4 + 3][tid];
            float top = fmaf(wxs[s][j], v01 - v00, v00);
            float bot = fmaf(wxs[s][j], v11 - v10, v10);
            float smp = fmaf(wys[s][j], bot - top, top);
            acc += fabsf(dds[s][j] - smp);
        }

        if (b + DEPTH < NB)
            issue_batch(b + DEPTH, tid, uf, vf, p, sMC, dsrc, ddst, tapbase,
                        d4buf, wxs, wys, dds);
    }

    // ---- block reduction ----
#pragma unroll
    for (int off = 16; off > 0; off >>= 1)
        acc += __shfl_down_sync(0xffffffffu, acc, off);

    __shared__ float warpsum[NTHR / 32];
    if ((tid & 31) == 0) warpsum[tid >> 5] = acc;
    __syncthreads();
    if (tid < 32) {
        float s = (tid < NTHR / 32) ? warpsum[tid] : 0.0f;
#pragma unroll
        for (int off = 2; off > 0; off >>= 1)
            s += __shfl_down_sync(0xffffffffu, s, off);
        if (tid == 0) {
            atomicAdd(&g_sum, (double)s);
            __threadfence();
            unsigned prev = atomicAdd(&g_count, 1u);
            if (prev == NBLOCKS - 1) {
                double total = atomicAdd(&g_sum, 0.0);
                out[0] = (float)(total * (1.0 / (double)((long long)NB * NPIX)));
                // reset for next graph replay (deterministic re-execution)
                g_sum   = 0.0;
                g_count = 0u;
                __threadfence();
            }
        }
    }
}

// ---------------------------------------------------------------------------
extern "C" void kernel_launch(void* const* d_in, const int* in_sizes, int n_in,
                              void* d_out, int out_size) {
    const float* depth0 = (const float*)d_in[0];
    const float* depth1 = (const float*)d_in[1];
    const float* R0     = (const float*)d_in[2];
    const float* t0     = (const float*)d_in[3];
    const float* R1     = (const float*)d_in[4];
    const float* t1     = (const float*)d_in[5];
    const float* K      = (const float*)d_in[6];

    dim3 grid(BLK_X, 2);
    pdsl_fused<<<grid, NTHR>>>(depth0, depth1, R0, t0, R1, t1, K, (float*)d_out);
}